// round 9
// baseline (speedup 1.0000x reference)
#include <cuda_runtime.h>
#include <math.h>
#include <stdint.h>

#define B 4
#define T 64
#define F 64
#define U 64
#define M 64
#define TF (T*F)
#define CPB 8          // CTAs per cluster (one cluster per batch)
#define RPC (T/CPB)    // 8 rows (t) per CTA
#define NTH 256

// Accurate tanh for value paths (h, ms): abs err ~1e-7.
__device__ __forceinline__ float fast_tanh(float x) {
    float e = __expf(2.0f * x);
    return 1.0f - __fdividef(2.0f, e + 1.0f);
}
// Single-MUFU f32 tanh for the argmax-only score path (proven argmax-safe).
__device__ __forceinline__ float tanh_mufu(float x) {
    float y; asm("tanh.approx.f32 %0, %1;" : "=f"(y) : "f"(x)); return y;
}
__device__ __forceinline__ uint32_t smem_u32(const void* p) {
    uint32_t a;
    asm("{ .reg .u64 t; cvta.to.shared.u64 t, %1; cvt.u32.u64 %0, t; }" : "=r"(a) : "l"(p));
    return a;
}
__device__ __forceinline__ void stc_f32(uint32_t saddr, int rank, float v) {
    uint32_t rr;
    asm volatile("mapa.shared::cluster.u32 %0, %1, %2;" : "=r"(rr) : "r"(saddr), "r"(rank));
    asm volatile("st.shared::cluster.f32 [%0], %1;" :: "r"(rr), "f"(v) : "memory");
}
__device__ __forceinline__ void stc_s32(uint32_t saddr, int rank, int v) {
    uint32_t rr;
    asm volatile("mapa.shared::cluster.u32 %0, %1, %2;" : "=r"(rr) : "r"(saddr), "r"(rank));
    asm volatile("st.shared::cluster.u32 [%0], %1;" :: "r"(rr), "r"(v) : "memory");
}
__device__ __forceinline__ void stc_u64(uint32_t saddr, int rank, unsigned long long v) {
    uint32_t rr;
    asm volatile("mapa.shared::cluster.u32 %0, %1, %2;" : "=r"(rr) : "r"(saddr), "r"(rank));
    asm volatile("st.shared::cluster.u64 [%0], %1;" :: "r"(rr), "l"(v) : "memory");
}
__device__ __forceinline__ void cluster_arrive() {
    asm volatile("barrier.cluster.arrive.aligned;" ::: "memory");
}
__device__ __forceinline__ void cluster_wait() {
    asm volatile("barrier.cluster.wait.aligned;" ::: "memory");
}

// =====================================================================
// Single fused kernel: cluster of 8 CTAs per batch, 8 warps per CTA.
// Phase1: warps 0-3 do both GEMMs for 2 rows each (halves Wk/Wv L1
// traffic); warps 4-7 prefetch mem_vals + w_s into smem.
// =====================================================================
__global__ void __launch_bounds__(NTH) __cluster_dims__(CPB, 1, 1)
fused_all(const float* __restrict__ inp,
          const float* __restrict__ Wk,
          const float* __restrict__ bk,
          const float* __restrict__ Wv,
          const float* __restrict__ bv,
          const float* __restrict__ w_s,
          const float* __restrict__ mem_keys,
          const float* __restrict__ mem_vals,
          float* __restrict__ d_out) {
    const int b    = blockIdx.x / CPB;
    const int r    = blockIdx.x % CPB;
    const int tid  = threadIdx.x;
    const int w    = tid >> 5;
    const int lane = tid & 31;
    const int tl   = w;            // local row this warp owns (score/dist)
    const int tg   = r*RPC + w;    // global t

    __shared__ __align__(16) float s_in[RPC][F];
    __shared__ float   s_h [RPC][U];
    __shared__ float   s_o [RPC][F];
    __shared__ float   s_sc[RPC][F];
    __shared__ __align__(16) float s_ms[RPC*F];
    __shared__ unsigned long long s_cand[CPB][F];  // [rank][f] (val<<32 | t)
    __shared__ int   s_idxt[T];
    __shared__ float s_lp[CPB][M];                 // [rank][m] logit partials
    __shared__ __align__(16) float s_mv[M][F];     // mem_vals staged
    __shared__ float s_ws[F];                      // w_s staged
    __shared__ float s_attn[M];
    __shared__ float s_tpart[4][F];
    __shared__ float s_amax[RPC], s_amin[RPC];
    __shared__ float s_wmm[2];
    __shared__ float s_imp;

    const float wlast = __ldg(w_s + 63);   // w_s[S-1]

    // ================= phase 1 =================
    if (w < 4) {
        const int rA = 2*w, rB = 2*w + 1;
        float2 iA = *(const float2*)(inp + (b*T + r*RPC + rA)*F + 2*lane);
        float2 iB = *(const float2*)(inp + (b*T + r*RPC + rB)*F + 2*lane);
        *(float2*)&s_in[rA][2*lane] = iA;
        *(float2*)&s_in[rB][2*lane] = iB;
        __syncwarp();

        // h = tanh(in @ Wk + bk), two rows at once
        const int u0 = 2*lane;
        float a00 = __ldg(bk + u0), a01 = __ldg(bk + u0 + 1);
        float a10 = a00, a11 = a01;
        #pragma unroll
        for (int f = 0; f < F; ++f) {
            float2 kk = *(const float2*)(Wk + f*U + u0);
            float xA = s_in[rA][f], xB = s_in[rB][f];
            a00 = fmaf(xA, kk.x, a00); a01 = fmaf(xA, kk.y, a01);
            a10 = fmaf(xB, kk.x, a10); a11 = fmaf(xB, kk.y, a11);
        }
        s_h[rA][u0] = fast_tanh(a00); s_h[rA][u0+1] = fast_tanh(a01);
        s_h[rB][u0] = fast_tanh(a10); s_h[rB][u0+1] = fast_tanh(a11);
        __syncwarp();

        // output = h @ Wv + bv, two rows at once
        const int f0 = 2*lane;
        float o00 = __ldg(bv + f0), o01 = __ldg(bv + f0 + 1);
        float o10 = o00, o11 = o01;
        #pragma unroll
        for (int u = 0; u < U; ++u) {
            float2 vv = *(const float2*)(Wv + u*F + f0);
            float hA = s_h[rA][u], hB = s_h[rB][u];
            o00 = fmaf(hA, vv.x, o00); o01 = fmaf(hA, vv.y, o01);
            o10 = fmaf(hB, vv.x, o10); o11 = fmaf(hB, vv.y, o11);
        }
        s_o[rA][f0] = o00; s_o[rA][f0+1] = o01;
        s_o[rB][f0] = o10; s_o[rB][f0+1] = o11;
        *(float2*)(d_out + 2*B*T + (b*T + r*RPC + rA)*F + f0) = make_float2(o00, o01);
        *(float2*)(d_out + 2*B*T + (b*T + r*RPC + rB)*F + f0) = make_float2(o10, o11);
    } else {
        // warps 4-7: stage mem_vals (16KB) and w_s into smem
        const float4* mv4  = (const float4*)mem_vals;
        float4*       smv4 = (float4*)s_mv;
        const int base = (w - 4)*32 + lane;   // 0..127
        #pragma unroll
        for (int k = 0; k < 8; ++k)
            smv4[base + k*128] = mv4[base + k*128];
        if (w == 4) s_ws[lane]      = w_s[lane];
        if (w == 5) s_ws[lane + 32] = w_s[lane + 32];
    }
    __syncthreads();

    // ================= score (all 8 warps, 1 row each) =================
    {
        const int f0 = 2*lane;
        const float c0 = s_o[tl][f0] * wlast, c1 = s_o[tl][f0+1] * wlast;
        float sc0 = 0.f, sc1 = 0.f;
        #pragma unroll
        for (int u = 0; u < U; ++u) {
            float hv = s_h[tl][u];
            sc0 += tanh_mufu(hv * c0);
            sc1 += tanh_mufu(hv * c1);
        }
        s_sc[tl][f0] = sc0; s_sc[tl][f0+1] = sc1;

        // idx_t[tg] = argmax_f (first max); 8 lanes push to all ranks
        float bvv = sc0; int bf = f0;
        if (sc1 > bvv) { bvv = sc1; bf = f0 + 1; }
        #pragma unroll
        for (int o = 16; o; o >>= 1) {
            float ov = __shfl_xor_sync(0xffffffffu, bvv, o);
            int   of = __shfl_xor_sync(0xffffffffu, bf,  o);
            if (ov > bvv || (ov == bvv && of < bf)) { bvv = ov; bf = of; }
        }
        if (lane < CPB)
            stc_s32(smem_u32(&s_idxt[tg]), lane, bf);
    }
    __syncthreads();

    // ---- per-f column-max candidate over local rows ----
    if (tid < F) {
        const int f = tid;
        float best = s_sc[0][f]; int bt = 0;
        #pragma unroll
        for (int t = 1; t < RPC; ++t) {
            float v = s_sc[t][f];
            if (v > best) { best = v; bt = t; }
        }
        unsigned long long c =
            ((unsigned long long)__float_as_uint(best) << 32) | (unsigned)(r*RPC + bt);
        uint32_t sa = smem_u32(&s_cand[r][f]);
        #pragma unroll
        for (int rr = 0; rr < CPB; ++rr) stc_u64(sa, rr, c);
    }
    cluster_arrive();
    cluster_wait();   // A: idx_t + candidates visible everywhere

    // ---- wmax/wmin (warp 0 handles both f-halves) ----
    if (w == 0) {
        float wv[2];
        #pragma unroll
        for (int hh = 0; hh < 2; ++hh) {
            const int f = lane + hh*32;
            unsigned long long c = s_cand[0][f];
            float best = __uint_as_float((unsigned)(c >> 32));
            int   bt   = (int)(c & 0xffffffffu);
            #pragma unroll
            for (int rr = 1; rr < CPB; ++rr) {
                unsigned long long cc = s_cand[rr][f];
                float v = __uint_as_float((unsigned)(cc >> 32));
                if (v > best) { best = v; bt = (int)(cc & 0xffffffffu); }
            }
            wv[hh] = s_ws[bt];
        }
        float mx = fmaxf(wv[0], wv[1]), mn = fminf(wv[0], wv[1]);
        #pragma unroll
        for (int o = 16; o; o >>= 1) {
            mx = fmaxf(mx, __shfl_xor_sync(0xffffffffu, mx, o));
            mn = fminf(mn, __shfl_xor_sync(0xffffffffu, mn, o));
        }
        if (lane == 0) { s_wmm[0] = mx; s_wmm[1] = mn; }
    }
    // ---- amax/amin per warp (own row) ----
    {
        float v0 = s_h[tl][s_idxt[lane]];
        float v1 = s_h[tl][s_idxt[lane + 32]];
        float mx = fmaxf(v0, v1), mn = fminf(v0, v1);
        #pragma unroll
        for (int o = 16; o; o >>= 1) {
            mx = fmaxf(mx, __shfl_xor_sync(0xffffffffu, mx, o));
            mn = fminf(mn, __shfl_xor_sync(0xffffffffu, mn, o));
        }
        if (lane == 0) { s_amax[tl] = mx; s_amin[tl] = mn; }
    }
    __syncthreads();

    // ---- ms for local rows ----
    {
        const float wmax = s_wmm[0], wmin = s_wmm[1];
        #pragma unroll
        for (int k = 0; k < 2; ++k) {
            const int i = tid + k*NTH;
            const int t = i >> 6;
            const float c   = s_o[t][i & 63];
            const float amx = s_amax[t], amn = s_amin[t];
            float m = fmaxf(fmaxf(amx*wmax*c, amx*wmin*c),
                            fmaxf(amn*wmax*c, amn*wmin*c));
            s_ms[i] = fast_tanh(m);
        }
    }
    __syncthreads();

    // ---- logit partials over this CTA's 512-element slice ----
    {
        const float4* __restrict__ ms4 = (const float4*)s_ms;
        #pragma unroll
        for (int k = 0; k < 8; ++k) {
            const int m = w*8 + k;
            const float4* __restrict__ key4 =
                (const float4*)(mem_keys + m*TF + r*(RPC*F));
            float p0 = 0.f, p1 = 0.f, p2 = 0.f, p3 = 0.f;
            #pragma unroll
            for (int c = 0; c < 4; ++c) {
                float4 kk = key4[c*32 + lane];
                float4 mm = ms4[c*32 + lane];
                p0 = fmaf(kk.x, mm.x, p0);
                p1 = fmaf(kk.y, mm.y, p1);
                p2 = fmaf(kk.z, mm.z, p2);
                p3 = fmaf(kk.w, mm.w, p3);
            }
            float acc = (p0 + p1) + (p2 + p3);
            #pragma unroll
            for (int o = 16; o; o >>= 1)
                acc += __shfl_xor_sync(0xffffffffu, acc, o);
            if (lane < CPB)
                stc_f32(smem_u32(&s_lp[r][m]), lane, acc);
        }
    }
    cluster_arrive();
    cluster_wait();   // B: all logit partials visible everywhere

    // ---- softmax / importance (single warp) ----
    if (w == 0) {
        float l0 = 0.f, l1 = 0.f;
        #pragma unroll
        for (int rr = 0; rr < CPB; ++rr) {
            l0 += s_lp[rr][lane];
            l1 += s_lp[rr][lane + 32];
        }
        float mx = fmaxf(l0, l1);
        #pragma unroll
        for (int o = 16; o; o >>= 1)
            mx = fmaxf(mx, __shfl_xor_sync(0xffffffffu, mx, o));
        float e0 = __expf(l0 - mx), e1 = __expf(l1 - mx);
        float s = e0 + e1;
        #pragma unroll
        for (int o = 16; o; o >>= 1)
            s += __shfl_xor_sync(0xffffffffu, s, o);
        float inv = 1.0f / s;
        s_attn[lane]      = e0 * inv;
        s_attn[lane + 32] = e1 * inv;
        if (lane == 0) s_imp = inv;   // max(attn) = exp(0)/sum
    }
    __syncthreads();

    // ---- targets partials: all 256 threads, 16 m each, from smem ----
    {
        const int f = tid & 63, q = tid >> 6;
        float acc = 0.f;
        #pragma unroll
        for (int mm = q*16; mm < q*16 + 16; ++mm)
            acc = fmaf(s_attn[mm], s_mv[mm][f], acc);
        s_tpart[q][f] = acc;
    }
    __syncthreads();

    // ---- dist + importances per warp row ----
    {
        float tg0 = (s_tpart[0][lane]      + s_tpart[1][lane])
                  + (s_tpart[2][lane]      + s_tpart[3][lane]);
        float tg1 = (s_tpart[0][lane + 32] + s_tpart[1][lane + 32])
                  + (s_tpart[2][lane + 32] + s_tpart[3][lane + 32]);
        float d0 = s_in[tl][lane]      - tg0;
        float d1 = s_in[tl][lane + 32] - tg1;
        float a2 = d0*d0 + d1*d1;
        #pragma unroll
        for (int o = 16; o; o >>= 1)
            a2 += __shfl_xor_sync(0xffffffffu, a2, o);
        if (lane == 0) {
            float nrm = sqrtf(a2);
            float hs  = fminf(fmaxf(0.2f*nrm + 0.5f, 0.f), 1.f);
            d_out[b*T + tg]       = 0.5f - hs;
            d_out[B*T + b*T + tg] = s_imp;
        }
    }
}

// =====================================================================
extern "C" void kernel_launch(void* const* d_in, const int* in_sizes, int n_in,
                              void* d_out, int out_size) {
    const float* inp      = (const float*)d_in[0];  // [B,T,F]
    const float* Wk       = (const float*)d_in[1];  // [F,U]
    const float* bk       = (const float*)d_in[2];  // [U]
    const float* Wv       = (const float*)d_in[3];  // [U,F]
    const float* bv       = (const float*)d_in[4];  // [F]
    const float* w_s      = (const float*)d_in[5];  // [S]
    const float* mem_keys = (const float*)d_in[6];  // [M, T*F]
    const float* mem_vals = (const float*)d_in[7];  // [M, F]

    fused_all<<<B*CPB, NTH>>>(inp, Wk, bk, Wv, bv, w_s, mem_keys, mem_vals,
                              (float*)d_out);
}

// round 10
// speedup vs baseline: 1.2704x; 1.2704x over previous
#include <cuda_runtime.h>
#include <math.h>
#include <stdint.h>

#define B 4
#define T 64
#define F 64
#define U 64
#define M 64
#define TF (T*F)
#define CPB 8          // CTAs per cluster (one cluster per batch)
#define RPC (T/CPB)    // 8 rows (t) per CTA
#define NTH 256

// Accurate tanh for value paths (h, ms): abs err ~1e-7.
__device__ __forceinline__ float fast_tanh(float x) {
    float e = __expf(2.0f * x);
    return 1.0f - __fdividef(2.0f, e + 1.0f);
}
// Single-MUFU f32 tanh for the argmax-only score path (proven argmax-safe).
__device__ __forceinline__ float tanh_mufu(float x) {
    float y; asm("tanh.approx.f32 %0, %1;" : "=f"(y) : "f"(x)); return y;
}
__device__ __forceinline__ uint32_t smem_u32(const void* p) {
    uint32_t a;
    asm("{ .reg .u64 t; cvta.to.shared.u64 t, %1; cvt.u32.u64 %0, t; }" : "=r"(a) : "l"(p));
    return a;
}
__device__ __forceinline__ void stc_f32(uint32_t saddr, int rank, float v) {
    uint32_t rr;
    asm volatile("mapa.shared::cluster.u32 %0, %1, %2;" : "=r"(rr) : "r"(saddr), "r"(rank));
    asm volatile("st.shared::cluster.f32 [%0], %1;" :: "r"(rr), "f"(v) : "memory");
}
__device__ __forceinline__ void stc_s32(uint32_t saddr, int rank, int v) {
    uint32_t rr;
    asm volatile("mapa.shared::cluster.u32 %0, %1, %2;" : "=r"(rr) : "r"(saddr), "r"(rank));
    asm volatile("st.shared::cluster.u32 [%0], %1;" :: "r"(rr), "r"(v) : "memory");
}
__device__ __forceinline__ void stc_u64(uint32_t saddr, int rank, unsigned long long v) {
    uint32_t rr;
    asm volatile("mapa.shared::cluster.u32 %0, %1, %2;" : "=r"(rr) : "r"(saddr), "r"(rank));
    asm volatile("st.shared::cluster.u64 [%0], %1;" :: "r"(rr), "l"(v) : "memory");
}
__device__ __forceinline__ void cluster_arrive() {
    asm volatile("barrier.cluster.arrive.aligned;" ::: "memory");
}
__device__ __forceinline__ void cluster_wait() {
    asm volatile("barrier.cluster.wait.aligned;" ::: "memory");
}

// =====================================================================
// Single fused kernel: cluster of 8 CTAs per batch, 8 warps per CTA,
// warp w owns row tg = rank*8 + w. Phase 1 (GEMMs + score + idx_t) is
// warp-private: only __syncwarp, so warps pipeline L1-bound GEMM work
// against MUFU-bound score work.
// =====================================================================
__global__ void __launch_bounds__(NTH) __cluster_dims__(CPB, 1, 1)
fused_all(const float* __restrict__ inp,
          const float* __restrict__ Wk,
          const float* __restrict__ bk,
          const float* __restrict__ Wv,
          const float* __restrict__ bv,
          const float* __restrict__ w_s,
          const float* __restrict__ mem_keys,
          const float* __restrict__ mem_vals,
          float* __restrict__ d_out) {
    const int b    = blockIdx.x / CPB;
    const int r    = blockIdx.x % CPB;
    const int tid  = threadIdx.x;
    const int w    = tid >> 5;
    const int lane = tid & 31;
    const int tl   = w;            // local row this warp owns
    const int tg   = r*RPC + w;    // global t

    __shared__ __align__(16) float s_in[RPC][F];
    __shared__ float   s_h [RPC][U];
    __shared__ float   s_o [RPC][F];
    __shared__ float   s_sc[RPC][F];
    __shared__ __align__(16) float s_ms[RPC*F];
    __shared__ unsigned long long s_cand[CPB][F];  // [rank][f] (val<<32 | t)
    __shared__ int   s_idxt[T];
    __shared__ float s_lp[CPB][M];                 // [rank][m] logit partials
    __shared__ float s_ws[F];                      // w_s staged
    __shared__ float s_attn[M];
    __shared__ float s_tpart[4][F];
    __shared__ float s_amax[RPC], s_amin[RPC];
    __shared__ float s_wmm[2];
    __shared__ float s_imp;

    // stage w_s early (used after barrier A)
    if (tid < F) s_ws[tid] = w_s[tid];

    const float wlast = __ldg(w_s + 63);   // w_s[S-1]

    // ================= phase 1 (warp-private, __syncwarp only) ========
    {
        // stage own input row
        float2 iv = *(const float2*)(inp + (b*T + tg)*F + 2*lane);
        *(float2*)&s_in[tl][2*lane] = iv;
        __syncwarp();

        // h = tanh(in @ Wk + bk)
        const int u0 = 2*lane;
        float a0 = __ldg(bk + u0), a1 = __ldg(bk + u0 + 1);
        #pragma unroll
        for (int f = 0; f < F; ++f) {
            float2 kk = *(const float2*)(Wk + f*U + u0);
            float x = s_in[tl][f];
            a0 = fmaf(x, kk.x, a0);
            a1 = fmaf(x, kk.y, a1);
        }
        s_h[tl][u0]   = fast_tanh(a0);
        s_h[tl][u0+1] = fast_tanh(a1);
        __syncwarp();

        // output = h @ Wv + bv
        const int f0 = 2*lane;
        float o0 = __ldg(bv + f0), o1 = __ldg(bv + f0 + 1);
        #pragma unroll
        for (int u = 0; u < U; ++u) {
            float2 vv = *(const float2*)(Wv + u*F + f0);
            float hv = s_h[tl][u];
            o0 = fmaf(hv, vv.x, o0);
            o1 = fmaf(hv, vv.y, o1);
        }
        s_o[tl][f0] = o0; s_o[tl][f0+1] = o1;
        *(float2*)(d_out + 2*B*T + (b*T + tg)*F + f0) = make_float2(o0, o1);
        __syncwarp();

        // score[f] = sum_u tanh(h[u]*out[f]*wlast)  (argmax-only)
        const float c0 = o0*wlast, c1 = o1*wlast;
        float sc0 = 0.f, sc1 = 0.f;
        #pragma unroll
        for (int u = 0; u < U; ++u) {
            float hv = s_h[tl][u];
            sc0 += tanh_mufu(hv * c0);
            sc1 += tanh_mufu(hv * c1);
        }
        s_sc[tl][f0] = sc0; s_sc[tl][f0+1] = sc1;

        // idx_t[tg] = argmax_f (first max); lanes 0-7 push to all ranks
        float bvv = sc0; int bf = f0;
        if (sc1 > bvv) { bvv = sc1; bf = f0 + 1; }
        #pragma unroll
        for (int o = 16; o; o >>= 1) {
            float ov = __shfl_xor_sync(0xffffffffu, bvv, o);
            int   of = __shfl_xor_sync(0xffffffffu, bf,  o);
            if (ov > bvv || (ov == bvv && of < bf)) { bvv = ov; bf = of; }
        }
        if (lane < CPB)
            stc_s32(smem_u32(&s_idxt[tg]), lane, bf);
    }
    __syncthreads();

    // ---- per-f column-max candidate over local rows ----
    if (tid < F) {
        const int f = tid;
        float best = s_sc[0][f]; int bt = 0;
        #pragma unroll
        for (int t = 1; t < RPC; ++t) {
            float v = s_sc[t][f];
            if (v > best) { best = v; bt = t; }
        }
        unsigned long long c =
            ((unsigned long long)__float_as_uint(best) << 32) | (unsigned)(r*RPC + bt);
        uint32_t sa = smem_u32(&s_cand[r][f]);
        #pragma unroll
        for (int rr = 0; rr < CPB; ++rr) stc_u64(sa, rr, c);
    }
    cluster_arrive();
    cluster_wait();   // A: idx_t + candidates visible everywhere

    // ---- wmax/wmin (warp 0, both f-halves) ----
    if (w == 0) {
        float wv[2];
        #pragma unroll
        for (int hh = 0; hh < 2; ++hh) {
            const int f = lane + hh*32;
            unsigned long long c = s_cand[0][f];
            float best = __uint_as_float((unsigned)(c >> 32));
            int   bt   = (int)(c & 0xffffffffu);
            #pragma unroll
            for (int rr = 1; rr < CPB; ++rr) {
                unsigned long long cc = s_cand[rr][f];
                float v = __uint_as_float((unsigned)(cc >> 32));
                if (v > best) { best = v; bt = (int)(cc & 0xffffffffu); }
            }
            wv[hh] = s_ws[bt];
        }
        float mx = fmaxf(wv[0], wv[1]), mn = fminf(wv[0], wv[1]);
        #pragma unroll
        for (int o = 16; o; o >>= 1) {
            mx = fmaxf(mx, __shfl_xor_sync(0xffffffffu, mx, o));
            mn = fminf(mn, __shfl_xor_sync(0xffffffffu, mn, o));
        }
        if (lane == 0) { s_wmm[0] = mx; s_wmm[1] = mn; }
    }
    // ---- amax/amin per warp (own row) ----
    {
        float v0 = s_h[tl][s_idxt[lane]];
        float v1 = s_h[tl][s_idxt[lane + 32]];
        float mx = fmaxf(v0, v1), mn = fminf(v0, v1);
        #pragma unroll
        for (int o = 16; o; o >>= 1) {
            mx = fmaxf(mx, __shfl_xor_sync(0xffffffffu, mx, o));
            mn = fminf(mn, __shfl_xor_sync(0xffffffffu, mn, o));
        }
        if (lane == 0) { s_amax[tl] = mx; s_amin[tl] = mn; }
    }
    __syncthreads();

    // ---- ms for local rows ----
    {
        const float wmax = s_wmm[0], wmin = s_wmm[1];
        #pragma unroll
        for (int k = 0; k < 2; ++k) {
            const int i = tid + k*NTH;
            const int t = i >> 6;
            const float c   = s_o[t][i & 63];
            const float amx = s_amax[t], amn = s_amin[t];
            float m = fmaxf(fmaxf(amx*wmax*c, amx*wmin*c),
                            fmaxf(amn*wmax*c, amn*wmin*c));
            s_ms[i] = fast_tanh(m);
        }
    }
    __syncthreads();

    // ---- logit partials over this CTA's 512-element slice ----
    {
        const float4* __restrict__ ms4 = (const float4*)s_ms;
        #pragma unroll
        for (int k = 0; k < 8; ++k) {
            const int m = w*8 + k;
            const float4* __restrict__ key4 =
                (const float4*)(mem_keys + m*TF + r*(RPC*F));
            float p0 = 0.f, p1 = 0.f, p2 = 0.f, p3 = 0.f;
            #pragma unroll
            for (int c = 0; c < 4; ++c) {
                float4 kk = key4[c*32 + lane];
                float4 mm = ms4[c*32 + lane];
                p0 = fmaf(kk.x, mm.x, p0);
                p1 = fmaf(kk.y, mm.y, p1);
                p2 = fmaf(kk.z, mm.z, p2);
                p3 = fmaf(kk.w, mm.w, p3);
            }
            float acc = (p0 + p1) + (p2 + p3);
            #pragma unroll
            for (int o = 16; o; o >>= 1)
                acc += __shfl_xor_sync(0xffffffffu, acc, o);
            if (lane < CPB)
                stc_f32(smem_u32(&s_lp[r][m]), lane, acc);
        }
    }
    cluster_arrive();
    cluster_wait();   // B: all logit partials visible everywhere

    // ---- softmax / importance (single warp) ----
    if (w == 0) {
        float l0 = 0.f, l1 = 0.f;
        #pragma unroll
        for (int rr = 0; rr < CPB; ++rr) {
            l0 += s_lp[rr][lane];
            l1 += s_lp[rr][lane + 32];
        }
        float mx = fmaxf(l0, l1);
        #pragma unroll
        for (int o = 16; o; o >>= 1)
            mx = fmaxf(mx, __shfl_xor_sync(0xffffffffu, mx, o));
        float e0 = __expf(l0 - mx), e1 = __expf(l1 - mx);
        float s = e0 + e1;
        #pragma unroll
        for (int o = 16; o; o >>= 1)
            s += __shfl_xor_sync(0xffffffffu, s, o);
        float inv = 1.0f / s;
        s_attn[lane]      = e0 * inv;
        s_attn[lane + 32] = e1 * inv;
        if (lane == 0) s_imp = inv;   // max(attn) = exp(0)/sum
    }
    __syncthreads();

    // ---- targets partials: 256 threads, 16 m each, direct from L2 ----
    {
        const int f = tid & 63, q = tid >> 6;
        float acc = 0.f;
        #pragma unroll
        for (int mm = q*16; mm < q*16 + 16; ++mm)
            acc = fmaf(s_attn[mm], __ldg(mem_vals + mm*F + f), acc);
        s_tpart[q][f] = acc;
    }
    __syncthreads();

    // ---- dist + importances per warp row ----
    {
        float tg0 = (s_tpart[0][lane]      + s_tpart[1][lane])
                  + (s_tpart[2][lane]      + s_tpart[3][lane]);
        float tg1 = (s_tpart[0][lane + 32] + s_tpart[1][lane + 32])
                  + (s_tpart[2][lane + 32] + s_tpart[3][lane + 32]);
        float d0 = s_in[tl][lane]      - tg0;
        float d1 = s_in[tl][lane + 32] - tg1;
        float a2 = d0*d0 + d1*d1;
        #pragma unroll
        for (int o = 16; o; o >>= 1)
            a2 += __shfl_xor_sync(0xffffffffu, a2, o);
        if (lane == 0) {
            float nrm = sqrtf(a2);
            float hs  = fminf(fmaxf(0.2f*nrm + 0.5f, 0.f), 1.f);
            d_out[b*T + tg]       = 0.5f - hs;
            d_out[B*T + b*T + tg] = s_imp;
        }
    }
}

// =====================================================================
extern "C" void kernel_launch(void* const* d_in, const int* in_sizes, int n_in,
                              void* d_out, int out_size) {
    const float* inp      = (const float*)d_in[0];  // [B,T,F]
    const float* Wk       = (const float*)d_in[1];  // [F,U]
    const float* bk       = (const float*)d_in[2];  // [U]
    const float* Wv       = (const float*)d_in[3];  // [U,F]
    const float* bv       = (const float*)d_in[4];  // [F]
    const float* w_s      = (const float*)d_in[5];  // [S]
    const float* mem_keys = (const float*)d_in[6];  // [M, T*F]
    const float* mem_vals = (const float*)d_in[7];  // [M, F]

    fused_all<<<B*CPB, NTH>>>(inp, Wk, bk, Wv, bv, w_s, mem_keys, mem_vals,
                              (float*)d_out);
}

// round 11
// speedup vs baseline: 1.2759x; 1.0043x over previous
#include <cuda_runtime.h>
#include <math.h>
#include <stdint.h>

#define B 4
#define T 64
#define F 64
#define U 64
#define M 64
#define TF (T*F)
#define CPB 8          // CTAs per cluster (one cluster per batch)
#define RPC (T/CPB)    // 8 rows (t) per CTA
#define NTH 256

// Accurate tanh for value paths (h, ms): abs err ~1e-7.
__device__ __forceinline__ float fast_tanh(float x) {
    float e = __expf(2.0f * x);
    return 1.0f - __fdividef(2.0f, e + 1.0f);
}
// Single-MUFU f32 tanh for the argmax-only score path (proven argmax-safe).
__device__ __forceinline__ float tanh_mufu(float x) {
    float y; asm("tanh.approx.f32 %0, %1;" : "=f"(y) : "f"(x)); return y;
}
__device__ __forceinline__ uint32_t smem_u32(const void* p) {
    uint32_t a;
    asm("{ .reg .u64 t; cvta.to.shared.u64 t, %1; cvt.u32.u64 %0, t; }" : "=r"(a) : "l"(p));
    return a;
}
__device__ __forceinline__ void stc_f32(uint32_t saddr, int rank, float v) {
    uint32_t rr;
    asm volatile("mapa.shared::cluster.u32 %0, %1, %2;" : "=r"(rr) : "r"(saddr), "r"(rank));
    asm volatile("st.shared::cluster.f32 [%0], %1;" :: "r"(rr), "f"(v) : "memory");
}
__device__ __forceinline__ void stc_s32(uint32_t saddr, int rank, int v) {
    uint32_t rr;
    asm volatile("mapa.shared::cluster.u32 %0, %1, %2;" : "=r"(rr) : "r"(saddr), "r"(rank));
    asm volatile("st.shared::cluster.u32 [%0], %1;" :: "r"(rr), "r"(v) : "memory");
}
__device__ __forceinline__ void stc_u64(uint32_t saddr, int rank, unsigned long long v) {
    uint32_t rr;
    asm volatile("mapa.shared::cluster.u32 %0, %1, %2;" : "=r"(rr) : "r"(saddr), "r"(rank));
    asm volatile("st.shared::cluster.u64 [%0], %1;" :: "r"(rr), "l"(v) : "memory");
}
__device__ __forceinline__ void cluster_arrive() {
    asm volatile("barrier.cluster.arrive.aligned;" ::: "memory");
}
__device__ __forceinline__ void cluster_wait() {
    asm volatile("barrier.cluster.wait.aligned;" ::: "memory");
}

// =====================================================================
// Single fused kernel: cluster of 8 CTAs per batch, 8 warps per CTA,
// warp w owns row tg = rank*8 + w. Phase 1 is warp-private (syncwarp
// only). Candidate all-to-all push distributed over all 8 warps.
// mem_vals prefetched into smem inside the barrier-A arrive/wait window.
// =====================================================================
__global__ void __launch_bounds__(NTH) __cluster_dims__(CPB, 1, 1)
fused_all(const float* __restrict__ inp,
          const float* __restrict__ Wk,
          const float* __restrict__ bk,
          const float* __restrict__ Wv,
          const float* __restrict__ bv,
          const float* __restrict__ w_s,
          const float* __restrict__ mem_keys,
          const float* __restrict__ mem_vals,
          float* __restrict__ d_out) {
    const int b    = blockIdx.x / CPB;
    const int r    = blockIdx.x % CPB;
    const int tid  = threadIdx.x;
    const int w    = tid >> 5;
    const int lane = tid & 31;
    const int tl   = w;            // local row this warp owns
    const int tg   = r*RPC + w;    // global t

    __shared__ __align__(16) float s_in[RPC][F];
    __shared__ float   s_h [RPC][U];
    __shared__ float   s_o [RPC][F];
    __shared__ float   s_sc[RPC][F];
    __shared__ __align__(16) float s_ms[RPC*F];
    __shared__ unsigned long long s_candloc[F];    // local per-f col-max
    __shared__ unsigned long long s_cand[CPB][F];  // [rank][f] (val<<32 | t)
    __shared__ int   s_idxt[T];
    __shared__ float s_lp[CPB][M];                 // [rank][m] logit partials
    __shared__ __align__(16) float s_mv[M][F];     // mem_vals staged (window A)
    __shared__ float s_ws[F];                      // w_s staged
    __shared__ float s_attn[M];
    __shared__ float s_tpart[4][F];
    __shared__ float s_amax[RPC], s_amin[RPC];
    __shared__ float s_wmm[2];
    __shared__ float s_imp;

    // stage w_s early (used after barrier A)
    if (tid < F) s_ws[tid] = w_s[tid];

    const float wlast = __ldg(w_s + 63);   // w_s[S-1]

    // ================= phase 1 (warp-private, __syncwarp only) ========
    {
        // stage own input row
        float2 iv = *(const float2*)(inp + (b*T + tg)*F + 2*lane);
        *(float2*)&s_in[tl][2*lane] = iv;
        __syncwarp();

        // h = tanh(in @ Wk + bk)
        const int u0 = 2*lane;
        float a0 = __ldg(bk + u0), a1 = __ldg(bk + u0 + 1);
        #pragma unroll
        for (int f = 0; f < F; ++f) {
            float2 kk = *(const float2*)(Wk + f*U + u0);
            float x = s_in[tl][f];
            a0 = fmaf(x, kk.x, a0);
            a1 = fmaf(x, kk.y, a1);
        }
        s_h[tl][u0]   = fast_tanh(a0);
        s_h[tl][u0+1] = fast_tanh(a1);
        __syncwarp();

        // output = h @ Wv + bv
        const int f0 = 2*lane;
        float o0 = __ldg(bv + f0), o1 = __ldg(bv + f0 + 1);
        #pragma unroll
        for (int u = 0; u < U; ++u) {
            float2 vv = *(const float2*)(Wv + u*F + f0);
            float hv = s_h[tl][u];
            o0 = fmaf(hv, vv.x, o0);
            o1 = fmaf(hv, vv.y, o1);
        }
        s_o[tl][f0] = o0; s_o[tl][f0+1] = o1;
        *(float2*)(d_out + 2*B*T + (b*T + tg)*F + f0) = make_float2(o0, o1);
        __syncwarp();

        // score[f] = sum_u tanh(h[u]*out[f]*wlast)  (argmax-only)
        const float c0 = o0*wlast, c1 = o1*wlast;
        float sc0 = 0.f, sc1 = 0.f;
        #pragma unroll
        for (int u = 0; u < U; ++u) {
            float hv = s_h[tl][u];
            sc0 += tanh_mufu(hv * c0);
            sc1 += tanh_mufu(hv * c1);
        }
        s_sc[tl][f0] = sc0; s_sc[tl][f0+1] = sc1;

        // idx_t[tg] = argmax_f (first max); lanes 0-7 push to all ranks
        float bvv = sc0; int bf = f0;
        if (sc1 > bvv) { bvv = sc1; bf = f0 + 1; }
        #pragma unroll
        for (int o = 16; o; o >>= 1) {
            float ov = __shfl_xor_sync(0xffffffffu, bvv, o);
            int   of = __shfl_xor_sync(0xffffffffu, bf,  o);
            if (ov > bvv || (ov == bvv && of < bf)) { bvv = ov; bf = of; }
        }
        if (lane < CPB)
            stc_s32(smem_u32(&s_idxt[tg]), lane, bf);
    }
    __syncthreads();

    // ---- per-f column-max candidate over local rows (into smem) ----
    if (tid < F) {
        const int f = tid;
        float best = s_sc[0][f]; int bt = 0;
        #pragma unroll
        for (int t = 1; t < RPC; ++t) {
            float v = s_sc[t][f];
            if (v > best) { best = v; bt = t; }
        }
        s_candloc[f] =
            ((unsigned long long)__float_as_uint(best) << 32) | (unsigned)(r*RPC + bt);
    }
    __syncthreads();

    // ---- push candidates: all 256 threads, 2 (f, rank) pairs each ----
    {
        #pragma unroll
        for (int k = 0; k < 2; ++k) {
            const int idx  = tid + k*NTH;       // 0..511
            const int f    = idx & 63;
            const int rank = idx >> 6;          // 0..7
            stc_u64(smem_u32(&s_cand[r][f]), rank, s_candloc[f]);
        }
    }
    cluster_arrive();

    // ---- window A: prefetch mem_vals (16KB) into smem ----
    {
        const float4* mv4  = (const float4*)mem_vals;
        float4*       smv4 = (float4*)s_mv;
        #pragma unroll
        for (int k = 0; k < 4; ++k)
            smv4[tid + k*NTH] = mv4[tid + k*NTH];
    }
    cluster_wait();   // A: idx_t + candidates visible everywhere

    // ---- wmax/wmin (warp 0, both f-halves) ----
    if (w == 0) {
        float wv[2];
        #pragma unroll
        for (int hh = 0; hh < 2; ++hh) {
            const int f = lane + hh*32;
            unsigned long long c = s_cand[0][f];
            float best = __uint_as_float((unsigned)(c >> 32));
            int   bt   = (int)(c & 0xffffffffu);
            #pragma unroll
            for (int rr = 1; rr < CPB; ++rr) {
                unsigned long long cc = s_cand[rr][f];
                float v = __uint_as_float((unsigned)(cc >> 32));
                if (v > best) { best = v; bt = (int)(cc & 0xffffffffu); }
            }
            wv[hh] = s_ws[bt];
        }
        float mx = fmaxf(wv[0], wv[1]), mn = fminf(wv[0], wv[1]);
        #pragma unroll
        for (int o = 16; o; o >>= 1) {
            mx = fmaxf(mx, __shfl_xor_sync(0xffffffffu, mx, o));
            mn = fminf(mn, __shfl_xor_sync(0xffffffffu, mn, o));
        }
        if (lane == 0) { s_wmm[0] = mx; s_wmm[1] = mn; }
    }
    // ---- amax/amin per warp (own row) ----
    {
        float v0 = s_h[tl][s_idxt[lane]];
        float v1 = s_h[tl][s_idxt[lane + 32]];
        float mx = fmaxf(v0, v1), mn = fminf(v0, v1);
        #pragma unroll
        for (int o = 16; o; o >>= 1) {
            mx = fmaxf(mx, __shfl_xor_sync(0xffffffffu, mx, o));
            mn = fminf(mn, __shfl_xor_sync(0xffffffffu, mn, o));
        }
        if (lane == 0) { s_amax[tl] = mx; s_amin[tl] = mn; }
    }
    __syncthreads();

    // ---- ms for local rows ----
    {
        const float wmax = s_wmm[0], wmin = s_wmm[1];
        #pragma unroll
        for (int k = 0; k < 2; ++k) {
            const int i = tid + k*NTH;
            const int t = i >> 6;
            const float c   = s_o[t][i & 63];
            const float amx = s_amax[t], amn = s_amin[t];
            float m = fmaxf(fmaxf(amx*wmax*c, amx*wmin*c),
                            fmaxf(amn*wmax*c, amn*wmin*c));
            s_ms[i] = fast_tanh(m);
        }
    }
    __syncthreads();

    // ---- logit partials over this CTA's 512-element slice ----
    {
        const float4* __restrict__ ms4 = (const float4*)s_ms;
        #pragma unroll
        for (int k = 0; k < 8; ++k) {
            const int m = w*8 + k;
            const float4* __restrict__ key4 =
                (const float4*)(mem_keys + m*TF + r*(RPC*F));
            float p0 = 0.f, p1 = 0.f, p2 = 0.f, p3 = 0.f;
            #pragma unroll
            for (int c = 0; c < 4; ++c) {
                float4 kk = key4[c*32 + lane];
                float4 mm = ms4[c*32 + lane];
                p0 = fmaf(kk.x, mm.x, p0);
                p1 = fmaf(kk.y, mm.y, p1);
                p2 = fmaf(kk.z, mm.z, p2);
                p3 = fmaf(kk.w, mm.w, p3);
            }
            float acc = (p0 + p1) + (p2 + p3);
            #pragma unroll
            for (int o = 16; o; o >>= 1)
                acc += __shfl_xor_sync(0xffffffffu, acc, o);
            if (lane < CPB)
                stc_f32(smem_u32(&s_lp[r][m]), lane, acc);
        }
    }
    cluster_arrive();
    cluster_wait();   // B: all logit partials visible everywhere

    // ---- softmax / importance (single warp) ----
    if (w == 0) {
        float l0 = 0.f, l1 = 0.f;
        #pragma unroll
        for (int rr = 0; rr < CPB; ++rr) {
            l0 += s_lp[rr][lane];
            l1 += s_lp[rr][lane + 32];
        }
        float mx = fmaxf(l0, l1);
        #pragma unroll
        for (int o = 16; o; o >>= 1)
            mx = fmaxf(mx, __shfl_xor_sync(0xffffffffu, mx, o));
        float e0 = __expf(l0 - mx), e1 = __expf(l1 - mx);
        float s = e0 + e1;
        #pragma unroll
        for (int o = 16; o; o >>= 1)
            s += __shfl_xor_sync(0xffffffffu, s, o);
        float inv = 1.0f / s;
        s_attn[lane]      = e0 * inv;
        s_attn[lane + 32] = e1 * inv;
        if (lane == 0) s_imp = inv;   // max(attn) = exp(0)/sum
    }
    __syncthreads();

    // ---- targets partials: 256 threads, 16 m each, from smem ----
    {
        const int f = tid & 63, q = tid >> 6;
        float acc = 0.f;
        #pragma unroll
        for (int mm = q*16; mm < q*16 + 16; ++mm)
            acc = fmaf(s_attn[mm], s_mv[mm][f], acc);
        s_tpart[q][f] = acc;
    }
    __syncthreads();

    // ---- dist + importances per warp row ----
    {
        float tg0 = (s_tpart[0][lane]      + s_tpart[1][lane])
                  + (s_tpart[2][lane]      + s_tpart[3][lane]);
        float tg1 = (s_tpart[0][lane + 32] + s_tpart[1][lane + 32])
                  + (s_tpart[2][lane + 32] + s_tpart[3][lane + 32]);
        float d0 = s_in[tl][lane]      - tg0;
        float d1 = s_in[tl][lane + 32] - tg1;
        float a2 = d0*d0 + d1*d1;
        #pragma unroll
        for (int o = 16; o; o >>= 1)
            a2 += __shfl_xor_sync(0xffffffffu, a2, o);
        if (lane == 0) {
            float nrm = sqrtf(a2);
            float hs  = fminf(fmaxf(0.2f*nrm + 0.5f, 0.f), 1.f);
            d_out[b*T + tg]       = 0.5f - hs;
            d_out[B*T + b*T + tg] = s_imp;
        }
    }
}

// =====================================================================
extern "C" void kernel_launch(void* const* d_in, const int* in_sizes, int n_in,
                              void* d_out, int out_size) {
    const float* inp      = (const float*)d_in[0];  // [B,T,F]
    const float* Wk       = (const float*)d_in[1];  // [F,U]
    const float* bk       = (const float*)d_in[2];  // [U]
    const float* Wv       = (const float*)d_in[3];  // [U,F]
    const float* bv       = (const float*)d_in[4];  // [F]
    const float* w_s      = (const float*)d_in[5];  // [S]
    const float* mem_keys = (const float*)d_in[6];  // [M, T*F]
    const float* mem_vals = (const float*)d_in[7];  // [M, F]

    fused_all<<<B*CPB, NTH>>>(inp, Wk, bk, Wv, bv, w_s, mem_keys, mem_vals,
                              (float*)d_out);
}

// round 12
// speedup vs baseline: 1.4129x; 1.1074x over previous
#include <cuda_runtime.h>
#include <math.h>
#include <stdint.h>

#define B 4
#define T 64
#define F 64
#define U 64
#define M 64
#define TF (T*F)
#define CPB 8          // CTAs per cluster (one cluster per batch)
#define RPC (T/CPB)    // 8 rows (t) per CTA
#define NTH 512        // 16 warps: warp-pair per row

// Accurate tanh for value paths (h, ms): abs err ~1e-7.
__device__ __forceinline__ float fast_tanh(float x) {
    float e = __expf(2.0f * x);
    return 1.0f - __fdividef(2.0f, e + 1.0f);
}
// Single-MUFU f32 tanh for the argmax-only score path (proven argmax-safe).
__device__ __forceinline__ float tanh_mufu(float x) {
    float y; asm("tanh.approx.f32 %0, %1;" : "=f"(y) : "f"(x)); return y;
}
__device__ __forceinline__ uint32_t smem_u32(const void* p) {
    uint32_t a;
    asm("{ .reg .u64 t; cvta.to.shared.u64 t, %1; cvt.u32.u64 %0, t; }" : "=r"(a) : "l"(p));
    return a;
}
__device__ __forceinline__ void stc_f32(uint32_t saddr, int rank, float v) {
    uint32_t rr;
    asm volatile("mapa.shared::cluster.u32 %0, %1, %2;" : "=r"(rr) : "r"(saddr), "r"(rank));
    asm volatile("st.shared::cluster.f32 [%0], %1;" :: "r"(rr), "f"(v) : "memory");
}
__device__ __forceinline__ void stc_s32(uint32_t saddr, int rank, int v) {
    uint32_t rr;
    asm volatile("mapa.shared::cluster.u32 %0, %1, %2;" : "=r"(rr) : "r"(saddr), "r"(rank));
    asm volatile("st.shared::cluster.u32 [%0], %1;" :: "r"(rr), "r"(v) : "memory");
}
__device__ __forceinline__ void stc_u64(uint32_t saddr, int rank, unsigned long long v) {
    uint32_t rr;
    asm volatile("mapa.shared::cluster.u32 %0, %1, %2;" : "=r"(rr) : "r"(saddr), "r"(rank));
    asm volatile("st.shared::cluster.u64 [%0], %1;" :: "r"(rr), "l"(v) : "memory");
}
__device__ __forceinline__ void cluster_arrive() {
    asm volatile("barrier.cluster.arrive.aligned;" ::: "memory");
}
__device__ __forceinline__ void cluster_wait() {
    asm volatile("barrier.cluster.wait.aligned;" ::: "memory");
}

// =====================================================================
// Cluster of 8 CTAs per batch, 16 warps per CTA (4/SMSP).
// Row tl (0..7) is owned by warp pair (2*tl, 2*tl+1): sub 0/1 split the
// reduction dimension of each phase-1 stage, halving dependent chains
// and doubling scheduler-visible warps.
// =====================================================================
__global__ void __launch_bounds__(NTH) __cluster_dims__(CPB, 1, 1)
fused_all(const float* __restrict__ inp,
          const float* __restrict__ Wk,
          const float* __restrict__ bk,
          const float* __restrict__ Wv,
          const float* __restrict__ bv,
          const float* __restrict__ w_s,
          const float* __restrict__ mem_keys,
          const float* __restrict__ mem_vals,
          float* __restrict__ d_out) {
    const int b    = blockIdx.x / CPB;
    const int r    = blockIdx.x % CPB;
    const int tid  = threadIdx.x;
    const int w    = tid >> 5;       // 0..15
    const int lane = tid & 31;
    const int tl   = w >> 1;         // row owned by this warp pair (0..7)
    const int sub  = w & 1;          // which half of the reduction dim

    __shared__ __align__(16) float s_in[RPC][F];
    __shared__ float   s_hp[2][RPC][U];   // h partials
    __shared__ float   s_h [RPC][U];
    __shared__ float   s_op[2][RPC][F];   // output partials
    __shared__ float   s_o [RPC][F];
    __shared__ float   s_scp[2][RPC][F];  // score partials
    __shared__ float   s_sc[RPC][F];
    __shared__ __align__(16) float s_ms[RPC*F];
    __shared__ unsigned long long s_candloc[F];
    __shared__ unsigned long long s_cand[CPB][F];  // [rank][f]
    __shared__ int   s_idxt[T];
    __shared__ float s_lp[CPB][M];
    __shared__ float s_ws[F];
    __shared__ float s_attn[M];
    __shared__ float s_tpart[8][F];
    __shared__ float s_amax[RPC], s_amin[RPC];
    __shared__ float s_wmm[2];
    __shared__ float s_imp;

    if (tid < F) s_ws[tid] = w_s[tid];
    const float wlast = __ldg(w_s + 63);

    // ---- stage inputs: 512 threads, 1 float each (coalesced) ----
    s_in[tid >> 6][tid & 63] = inp[(b*T + r*RPC)*F + tid];
    __syncthreads();

    // ---- h partials: warp pair splits f; u0 = 2*lane ----
    {
        const int fbase = sub*32;
        const int u0 = 2*lane;
        float a0 = 0.f, a1 = 0.f;
        #pragma unroll
        for (int f = 0; f < 32; ++f) {
            float2 kk = *(const float2*)(Wk + (fbase + f)*U + u0);
            float x = s_in[tl][fbase + f];
            a0 = fmaf(x, kk.x, a0);
            a1 = fmaf(x, kk.y, a1);
        }
        s_hp[sub][tl][u0] = a0; s_hp[sub][tl][u0+1] = a1;
    }
    __syncthreads();
    // combine h: thread (tl,u)
    {
        const int t = tid >> 6, u = tid & 63;
        s_h[t][u] = fast_tanh(__ldg(bk + u) + s_hp[0][t][u] + s_hp[1][t][u]);
    }
    __syncthreads();

    // ---- output partials: warp pair splits u; f0 = 2*lane ----
    {
        const int ubase = sub*32;
        const int f0 = 2*lane;
        float o0 = 0.f, o1 = 0.f;
        #pragma unroll
        for (int u = 0; u < 32; ++u) {
            float2 vv = *(const float2*)(Wv + (ubase + u)*F + f0);
            float hv = s_h[tl][ubase + u];
            o0 = fmaf(hv, vv.x, o0);
            o1 = fmaf(hv, vv.y, o1);
        }
        s_op[sub][tl][f0] = o0; s_op[sub][tl][f0+1] = o1;
    }
    __syncthreads();
    // combine output: thread (t,f); store third output
    {
        const int t = tid >> 6, f = tid & 63;
        float o = __ldg(bv + f) + s_op[0][t][f] + s_op[1][t][f];
        s_o[t][f] = o;
        d_out[2*B*T + (b*T + r*RPC)*F + tid] = o;
    }
    __syncthreads();

    // ---- score partials: warp pair splits u; f0 = 2*lane ----
    {
        const int ubase = sub*32;
        const int f0 = 2*lane;
        const float c0 = s_o[tl][f0] * wlast, c1 = s_o[tl][f0+1] * wlast;
        float sc0 = 0.f, sc1 = 0.f;
        #pragma unroll
        for (int u = 0; u < 32; ++u) {
            float hv = s_h[tl][ubase + u];
            sc0 += tanh_mufu(hv * c0);
            sc1 += tanh_mufu(hv * c1);
        }
        s_scp[sub][tl][f0] = sc0; s_scp[sub][tl][f0+1] = sc1;
    }
    __syncthreads();
    // combine score: thread (t,f)
    {
        const int t = tid >> 6, f = tid & 63;
        s_sc[t][f] = s_scp[0][t][f] + s_scp[1][t][f];
    }
    __syncthreads();

    // ---- idx_t: warps 0-7, row = w; argmax_f (first max) ----
    if (w < RPC) {
        const int f0 = 2*lane;
        float sc0 = s_sc[w][f0], sc1 = s_sc[w][f0+1];
        float bvv = sc0; int bf = f0;
        if (sc1 > bvv) { bvv = sc1; bf = f0 + 1; }
        #pragma unroll
        for (int o = 16; o; o >>= 1) {
            float ov = __shfl_xor_sync(0xffffffffu, bvv, o);
            int   of = __shfl_xor_sync(0xffffffffu, bf,  o);
            if (ov > bvv || (ov == bvv && of < bf)) { bvv = ov; bf = of; }
        }
        if (lane < CPB)
            stc_s32(smem_u32(&s_idxt[r*RPC + w]), lane, bf);
    }
    // ---- per-f column-max candidate over local rows ----
    else if (w < RPC + 2) {
        const int f = (w - RPC)*32 + lane;   // warps 8,9 cover f 0..63
        float best = s_sc[0][f]; int bt = 0;
        #pragma unroll
        for (int t = 1; t < RPC; ++t) {
            float v = s_sc[t][f];
            if (v > best) { best = v; bt = t; }
        }
        s_candloc[f] =
            ((unsigned long long)__float_as_uint(best) << 32) | (unsigned)(r*RPC + bt);
    }
    __syncthreads();

    // ---- push candidates: 512 threads, 1 (f, rank) pair each ----
    stc_u64(smem_u32(&s_cand[r][tid & 63]), tid >> 6, s_candloc[tid & 63]);
    cluster_arrive();
    cluster_wait();   // A: idx_t + candidates visible everywhere

    // ---- wmax/wmin (warp 0) ----
    if (w == 0) {
        float wv[2];
        #pragma unroll
        for (int hh = 0; hh < 2; ++hh) {
            const int f = lane + hh*32;
            unsigned long long c = s_cand[0][f];
            float best = __uint_as_float((unsigned)(c >> 32));
            int   bt   = (int)(c & 0xffffffffu);
            #pragma unroll
            for (int rr = 1; rr < CPB; ++rr) {
                unsigned long long cc = s_cand[rr][f];
                float v = __uint_as_float((unsigned)(cc >> 32));
                if (v > best) { best = v; bt = (int)(cc & 0xffffffffu); }
            }
            wv[hh] = s_ws[bt];
        }
        float mx = fmaxf(wv[0], wv[1]), mn = fminf(wv[0], wv[1]);
        #pragma unroll
        for (int o = 16; o; o >>= 1) {
            mx = fmaxf(mx, __shfl_xor_sync(0xffffffffu, mx, o));
            mn = fminf(mn, __shfl_xor_sync(0xffffffffu, mn, o));
        }
        if (lane == 0) { s_wmm[0] = mx; s_wmm[1] = mn; }
    }
    // ---- amax/amin: warps 8-15, row = w-8 ----
    else if (w >= 8) {
        const int t = w - 8;
        float v0 = s_h[t][s_idxt[lane]];
        float v1 = s_h[t][s_idxt[lane + 32]];
        float mx = fmaxf(v0, v1), mn = fminf(v0, v1);
        #pragma unroll
        for (int o = 16; o; o >>= 1) {
            mx = fmaxf(mx, __shfl_xor_sync(0xffffffffu, mx, o));
            mn = fminf(mn, __shfl_xor_sync(0xffffffffu, mn, o));
        }
        if (lane == 0) { s_amax[t] = mx; s_amin[t] = mn; }
    }
    __syncthreads();

    // ---- ms: 512 threads, 1 element each ----
    {
        const int t = tid >> 6;
        const float c   = s_o[t][tid & 63];
        const float wmax = s_wmm[0], wmin = s_wmm[1];
        const float amx = s_amax[t], amn = s_amin[t];
        float m = fmaxf(fmaxf(amx*wmax*c, amx*wmin*c),
                        fmaxf(amn*wmax*c, amn*wmin*c));
        s_ms[tid] = fast_tanh(m);
    }
    __syncthreads();

    // ---- logit partials: 16 warps, 4 m each ----
    {
        const float4* __restrict__ ms4 = (const float4*)s_ms;
        #pragma unroll
        for (int k = 0; k < 4; ++k) {
            const int m = w*4 + k;
            const float4* __restrict__ key4 =
                (const float4*)(mem_keys + m*TF + r*(RPC*F));
            float p0 = 0.f, p1 = 0.f, p2 = 0.f, p3 = 0.f;
            #pragma unroll
            for (int c = 0; c < 4; ++c) {
                float4 kk = key4[c*32 + lane];
                float4 mm = ms4[c*32 + lane];
                p0 = fmaf(kk.x, mm.x, p0);
                p1 = fmaf(kk.y, mm.y, p1);
                p2 = fmaf(kk.z, mm.z, p2);
                p3 = fmaf(kk.w, mm.w, p3);
            }
            float acc = (p0 + p1) + (p2 + p3);
            #pragma unroll
            for (int o = 16; o; o >>= 1)
                acc += __shfl_xor_sync(0xffffffffu, acc, o);
            if (lane < CPB)
                stc_f32(smem_u32(&s_lp[r][m]), lane, acc);
        }
    }
    cluster_arrive();
    cluster_wait();   // B: all logit partials visible everywhere

    // ---- softmax / importance (single warp) ----
    if (w == 0) {
        float l0 = 0.f, l1 = 0.f;
        #pragma unroll
        for (int rr = 0; rr < CPB; ++rr) {
            l0 += s_lp[rr][lane];
            l1 += s_lp[rr][lane + 32];
        }
        float mx = fmaxf(l0, l1);
        #pragma unroll
        for (int o = 16; o; o >>= 1)
            mx = fmaxf(mx, __shfl_xor_sync(0xffffffffu, mx, o));
        float e0 = __expf(l0 - mx), e1 = __expf(l1 - mx);
        float s = e0 + e1;
        #pragma unroll
        for (int o = 16; o; o >>= 1)
            s += __shfl_xor_sync(0xffffffffu, s, o);
        float inv = 1.0f / s;
        s_attn[lane]      = e0 * inv;
        s_attn[lane + 32] = e1 * inv;
        if (lane == 0) s_imp = inv;   // max(attn) = exp(0)/sum
    }
    __syncthreads();

    // ---- targets partials: 512 threads, 8 m each ----
    {
        const int f = tid & 63, q = tid >> 6;
        float acc = 0.f;
        #pragma unroll
        for (int mm = q*8; mm < q*8 + 8; ++mm)
            acc = fmaf(s_attn[mm], __ldg(mem_vals + mm*F + f), acc);
        s_tpart[q][f] = acc;
    }
    __syncthreads();

    // ---- dist + importances: warps 0-7, row = w ----
    if (w < RPC) {
        float tg0 = 0.f, tg1 = 0.f;
        #pragma unroll
        for (int q = 0; q < 8; ++q) {
            tg0 += s_tpart[q][lane];
            tg1 += s_tpart[q][lane + 32];
        }
        float d0 = s_in[w][lane]      - tg0;
        float d1 = s_in[w][lane + 32] - tg1;
        float a2 = d0*d0 + d1*d1;
        #pragma unroll
        for (int o = 16; o; o >>= 1)
            a2 += __shfl_xor_sync(0xffffffffu, a2, o);
        if (lane == 0) {
            float nrm = sqrtf(a2);
            float hs  = fminf(fmaxf(0.2f*nrm + 0.5f, 0.f), 1.f);
            d_out[b*T + r*RPC + w]       = 0.5f - hs;
            d_out[B*T + b*T + r*RPC + w] = s_imp;
        }
    }
}

// =====================================================================
extern "C" void kernel_launch(void* const* d_in, const int* in_sizes, int n_in,
                              void* d_out, int out_size) {
    const float* inp      = (const float*)d_in[0];  // [B,T,F]
    const float* Wk       = (const float*)d_in[1];  // [F,U]
    const float* bk       = (const float*)d_in[2];  // [U]
    const float* Wv       = (const float*)d_in[3];  // [U,F]
    const float* bv       = (const float*)d_in[4];  // [F]
    const float* w_s      = (const float*)d_in[5];  // [S]
    const float* mem_keys = (const float*)d_in[6];  // [M, T*F]
    const float* mem_vals = (const float*)d_in[7];  // [M, F]

    fused_all<<<B*CPB, NTH>>>(inp, Wk, bk, Wv, bv, w_s, mem_keys, mem_vals,
                              (float*)d_out);
}

// round 13
// speedup vs baseline: 1.4837x; 1.0501x over previous
#include <cuda_runtime.h>
#include <math.h>
#include <stdint.h>

#define B 4
#define T 64
#define F 64
#define U 64
#define M 64
#define TF (T*F)
#define CPB 8          // CTAs per cluster (one cluster per batch)
#define RPC (T/CPB)    // 8 rows (t) per CTA
#define NTH 1024       // 32 warps: warp-quad per row

// Accurate tanh for value paths (h, ms): abs err ~1e-7.
__device__ __forceinline__ float fast_tanh(float x) {
    float e = __expf(2.0f * x);
    return 1.0f - __fdividef(2.0f, e + 1.0f);
}
// Single-MUFU f32 tanh for the argmax-only score path (proven argmax-safe).
__device__ __forceinline__ float tanh_mufu(float x) {
    float y; asm("tanh.approx.f32 %0, %1;" : "=f"(y) : "f"(x)); return y;
}
__device__ __forceinline__ uint32_t smem_u32(const void* p) {
    uint32_t a;
    asm("{ .reg .u64 t; cvta.to.shared.u64 t, %1; cvt.u32.u64 %0, t; }" : "=r"(a) : "l"(p));
    return a;
}
__device__ __forceinline__ void stc_f32(uint32_t saddr, int rank, float v) {
    uint32_t rr;
    asm volatile("mapa.shared::cluster.u32 %0, %1, %2;" : "=r"(rr) : "r"(saddr), "r"(rank));
    asm volatile("st.shared::cluster.f32 [%0], %1;" :: "r"(rr), "f"(v) : "memory");
}
__device__ __forceinline__ void stc_s32(uint32_t saddr, int rank, int v) {
    uint32_t rr;
    asm volatile("mapa.shared::cluster.u32 %0, %1, %2;" : "=r"(rr) : "r"(saddr), "r"(rank));
    asm volatile("st.shared::cluster.u32 [%0], %1;" :: "r"(rr), "r"(v) : "memory");
}
__device__ __forceinline__ void stc_u64(uint32_t saddr, int rank, unsigned long long v) {
    uint32_t rr;
    asm volatile("mapa.shared::cluster.u32 %0, %1, %2;" : "=r"(rr) : "r"(saddr), "r"(rank));
    asm volatile("st.shared::cluster.u64 [%0], %1;" :: "r"(rr), "l"(v) : "memory");
}
__device__ __forceinline__ void cluster_arrive() {
    asm volatile("barrier.cluster.arrive.aligned;" ::: "memory");
}
__device__ __forceinline__ void cluster_wait() {
    asm volatile("barrier.cluster.wait.aligned;" ::: "memory");
}

// =====================================================================
// Cluster of 8 CTAs per batch, 32 warps per CTA (8/SMSP).
// Row tl (0..7) is owned by warp quad (4*tl..4*tl+3): sub 0..3 split the
// reduction dimension of each phase-1 stage into 16-iteration chains.
// =====================================================================
__global__ void __launch_bounds__(NTH) __cluster_dims__(CPB, 1, 1)
fused_all(const float* __restrict__ inp,
          const float* __restrict__ Wk,
          const float* __restrict__ bk,
          const float* __restrict__ Wv,
          const float* __restrict__ bv,
          const float* __restrict__ w_s,
          const float* __restrict__ mem_keys,
          const float* __restrict__ mem_vals,
          float* __restrict__ d_out) {
    const int b    = blockIdx.x / CPB;
    const int r    = blockIdx.x % CPB;
    const int tid  = threadIdx.x;
    const int w    = tid >> 5;       // 0..31
    const int lane = tid & 31;
    const int tl   = w >> 2;         // row owned by this warp quad (0..7)
    const int sub  = w & 3;          // quarter of the reduction dim

    __shared__ __align__(16) float s_in[RPC][F];
    __shared__ float   s_hp[4][RPC][U];   // h partials
    __shared__ float   s_h [RPC][U];
    __shared__ float   s_op[4][RPC][F];   // output partials
    __shared__ float   s_o [RPC][F];
    __shared__ float   s_scp[4][RPC][F];  // score partials
    __shared__ float   s_sc[RPC][F];
    __shared__ __align__(16) float s_ms[RPC*F];
    __shared__ unsigned long long s_candloc[F];
    __shared__ unsigned long long s_cand[CPB][F];  // [rank][f]
    __shared__ int   s_idxt[T];
    __shared__ float s_lp[CPB][M];
    __shared__ float s_ws[F];
    __shared__ float s_attn[M];
    __shared__ float s_tpart[16][F];
    __shared__ float s_amax[RPC], s_amin[RPC];
    __shared__ float s_wmm[2];
    __shared__ float s_imp;

    if (tid < F) s_ws[tid] = w_s[tid];
    const float wlast = __ldg(w_s + 63);

    // ---- stage inputs: 512 floats ----
    if (tid < RPC*F)
        s_in[tid >> 6][tid & 63] = inp[(b*T + r*RPC)*F + tid];
    __syncthreads();

    // ---- h partials: quad splits f (16 each); u0 = 2*lane ----
    {
        const int fbase = sub*16;
        const int u0 = 2*lane;
        float a0 = 0.f, a1 = 0.f;
        #pragma unroll
        for (int f = 0; f < 16; ++f) {
            float2 kk = *(const float2*)(Wk + (fbase + f)*U + u0);
            float x = s_in[tl][fbase + f];
            a0 = fmaf(x, kk.x, a0);
            a1 = fmaf(x, kk.y, a1);
        }
        s_hp[sub][tl][u0] = a0; s_hp[sub][tl][u0+1] = a1;
    }
    __syncthreads();
    if (tid < RPC*U) {
        const int t = tid >> 6, u = tid & 63;
        s_h[t][u] = fast_tanh(__ldg(bk + u) +
                    (s_hp[0][t][u] + s_hp[1][t][u]) +
                    (s_hp[2][t][u] + s_hp[3][t][u]));
    }
    __syncthreads();

    // ---- output partials: quad splits u (16 each); f0 = 2*lane ----
    {
        const int ubase = sub*16;
        const int f0 = 2*lane;
        float o0 = 0.f, o1 = 0.f;
        #pragma unroll
        for (int u = 0; u < 16; ++u) {
            float2 vv = *(const float2*)(Wv + (ubase + u)*F + f0);
            float hv = s_h[tl][ubase + u];
            o0 = fmaf(hv, vv.x, o0);
            o1 = fmaf(hv, vv.y, o1);
        }
        s_op[sub][tl][f0] = o0; s_op[sub][tl][f0+1] = o1;
    }
    __syncthreads();
    if (tid < RPC*F) {
        const int t = tid >> 6, f = tid & 63;
        float o = __ldg(bv + f) +
                  (s_op[0][t][f] + s_op[1][t][f]) +
                  (s_op[2][t][f] + s_op[3][t][f]);
        s_o[t][f] = o;
        d_out[2*B*T + (b*T + r*RPC)*F + tid] = o;
    }
    __syncthreads();

    // ---- score partials: quad splits u (16 each); f0 = 2*lane ----
    {
        const int ubase = sub*16;
        const int f0 = 2*lane;
        const float c0 = s_o[tl][f0] * wlast, c1 = s_o[tl][f0+1] * wlast;
        float sc0 = 0.f, sc1 = 0.f;
        #pragma unroll
        for (int u = 0; u < 16; ++u) {
            float hv = s_h[tl][ubase + u];
            sc0 += tanh_mufu(hv * c0);
            sc1 += tanh_mufu(hv * c1);
        }
        s_scp[sub][tl][f0] = sc0; s_scp[sub][tl][f0+1] = sc1;
    }
    __syncthreads();
    if (tid < RPC*F) {
        const int t = tid >> 6, f = tid & 63;
        s_sc[t][f] = (s_scp[0][t][f] + s_scp[1][t][f]) +
                     (s_scp[2][t][f] + s_scp[3][t][f]);
    }
    __syncthreads();

    // ---- idx_t: warps 0-7, row = w; argmax_f (first max) ----
    if (w < RPC) {
        const int f0 = 2*lane;
        float sc0 = s_sc[w][f0], sc1 = s_sc[w][f0+1];
        float bvv = sc0; int bf = f0;
        if (sc1 > bvv) { bvv = sc1; bf = f0 + 1; }
        #pragma unroll
        for (int o = 16; o; o >>= 1) {
            float ov = __shfl_xor_sync(0xffffffffu, bvv, o);
            int   of = __shfl_xor_sync(0xffffffffu, bf,  o);
            if (ov > bvv || (ov == bvv && of < bf)) { bvv = ov; bf = of; }
        }
        if (lane < CPB)
            stc_s32(smem_u32(&s_idxt[r*RPC + w]), lane, bf);
    }
    // ---- per-f column-max candidate over local rows (warps 8,9) ----
    else if (w < RPC + 2) {
        const int f = (w - RPC)*32 + lane;
        float best = s_sc[0][f]; int bt = 0;
        #pragma unroll
        for (int t = 1; t < RPC; ++t) {
            float v = s_sc[t][f];
            if (v > best) { best = v; bt = t; }
        }
        s_candloc[f] =
            ((unsigned long long)__float_as_uint(best) << 32) | (unsigned)(r*RPC + bt);
    }
    __syncthreads();

    // ---- push candidates: 512 threads, 1 (f, rank) pair each ----
    if (tid < F*CPB)
        stc_u64(smem_u32(&s_cand[r][tid & 63]), tid >> 6, s_candloc[tid & 63]);
    cluster_arrive();
    cluster_wait();   // A: idx_t + candidates visible everywhere

    // ---- wmax/wmin (warp 0) ----
    if (w == 0) {
        float wv[2];
        #pragma unroll
        for (int hh = 0; hh < 2; ++hh) {
            const int f = lane + hh*32;
            unsigned long long c = s_cand[0][f];
            float best = __uint_as_float((unsigned)(c >> 32));
            int   bt   = (int)(c & 0xffffffffu);
            #pragma unroll
            for (int rr = 1; rr < CPB; ++rr) {
                unsigned long long cc = s_cand[rr][f];
                float v = __uint_as_float((unsigned)(cc >> 32));
                if (v > best) { best = v; bt = (int)(cc & 0xffffffffu); }
            }
            wv[hh] = s_ws[bt];
        }
        float mx = fmaxf(wv[0], wv[1]), mn = fminf(wv[0], wv[1]);
        #pragma unroll
        for (int o = 16; o; o >>= 1) {
            mx = fmaxf(mx, __shfl_xor_sync(0xffffffffu, mx, o));
            mn = fminf(mn, __shfl_xor_sync(0xffffffffu, mn, o));
        }
        if (lane == 0) { s_wmm[0] = mx; s_wmm[1] = mn; }
    }
    // ---- amax/amin: warps 8-15, row = w-8 ----
    else if (w >= 8 && w < 16) {
        const int t = w - 8;
        float v0 = s_h[t][s_idxt[lane]];
        float v1 = s_h[t][s_idxt[lane + 32]];
        float mx = fmaxf(v0, v1), mn = fminf(v0, v1);
        #pragma unroll
        for (int o = 16; o; o >>= 1) {
            mx = fmaxf(mx, __shfl_xor_sync(0xffffffffu, mx, o));
            mn = fminf(mn, __shfl_xor_sync(0xffffffffu, mn, o));
        }
        if (lane == 0) { s_amax[t] = mx; s_amin[t] = mn; }
    }
    __syncthreads();

    // ---- ms: 512 threads, 1 element each ----
    if (tid < RPC*F) {
        const int t = tid >> 6;
        const float c   = s_o[t][tid & 63];
        const float wmax = s_wmm[0], wmin = s_wmm[1];
        const float amx = s_amax[t], amn = s_amin[t];
        float m = fmaxf(fmaxf(amx*wmax*c, amx*wmin*c),
                        fmaxf(amn*wmax*c, amn*wmin*c));
        s_ms[tid] = fast_tanh(m);
    }
    __syncthreads();

    // ---- logit partials: 32 warps, 2 m each ----
    {
        const float4* __restrict__ ms4 = (const float4*)s_ms;
        #pragma unroll
        for (int k = 0; k < 2; ++k) {
            const int m = w*2 + k;
            const float4* __restrict__ key4 =
                (const float4*)(mem_keys + m*TF + r*(RPC*F));
            float p0 = 0.f, p1 = 0.f, p2 = 0.f, p3 = 0.f;
            #pragma unroll
            for (int c = 0; c < 4; ++c) {
                float4 kk = key4[c*32 + lane];
                float4 mm = ms4[c*32 + lane];
                p0 = fmaf(kk.x, mm.x, p0);
                p1 = fmaf(kk.y, mm.y, p1);
                p2 = fmaf(kk.z, mm.z, p2);
                p3 = fmaf(kk.w, mm.w, p3);
            }
            float acc = (p0 + p1) + (p2 + p3);
            #pragma unroll
            for (int o = 16; o; o >>= 1)
                acc += __shfl_xor_sync(0xffffffffu, acc, o);
            if (lane < CPB)
                stc_f32(smem_u32(&s_lp[r][m]), lane, acc);
        }
    }
    cluster_arrive();
    cluster_wait();   // B: all logit partials visible everywhere

    // ---- softmax / importance (single warp) ----
    if (w == 0) {
        float l0 = 0.f, l1 = 0.f;
        #pragma unroll
        for (int rr = 0; rr < CPB; ++rr) {
            l0 += s_lp[rr][lane];
            l1 += s_lp[rr][lane + 32];
        }
        float mx = fmaxf(l0, l1);
        #pragma unroll
        for (int o = 16; o; o >>= 1)
            mx = fmaxf(mx, __shfl_xor_sync(0xffffffffu, mx, o));
        float e0 = __expf(l0 - mx), e1 = __expf(l1 - mx);
        float s = e0 + e1;
        #pragma unroll
        for (int o = 16; o; o >>= 1)
            s += __shfl_xor_sync(0xffffffffu, s, o);
        float inv = 1.0f / s;
        s_attn[lane]      = e0 * inv;
        s_attn[lane + 32] = e1 * inv;
        if (lane == 0) s_imp = inv;   // max(attn) = exp(0)/sum
    }
    __syncthreads();

    // ---- targets partials: 1024 threads, 4 m each ----
    {
        const int f = tid & 63, q = tid >> 6;   // q = 0..15
        float acc = 0.f;
        #pragma unroll
        for (int mm = q*4; mm < q*4 + 4; ++mm)
            acc = fmaf(s_attn[mm], __ldg(mem_vals + mm*F + f), acc);
        s_tpart[q][f] = acc;
    }
    __syncthreads();

    // ---- dist + importances: warps 0-7, row = w ----
    if (w < RPC) {
        float tg0 = 0.f, tg1 = 0.f;
        #pragma unroll
        for (int q = 0; q < 16; ++q) {
            tg0 += s_tpart[q][lane];
            tg1 += s_tpart[q][lane + 32];
        }
        float d0 = s_in[w][lane]      - tg0;
        float d1 = s_in[w][lane + 32] - tg1;
        float a2 = d0*d0 + d1*d1;
        #pragma unroll
        for (int o = 16; o; o >>= 1)
            a2 += __shfl_xor_sync(0xffffffffu, a2, o);
        if (lane == 0) {
            float nrm = sqrtf(a2);
            float hs  = fminf(fmaxf(0.2f*nrm + 0.5f, 0.f), 1.f);
            d_out[b*T + r*RPC + w]       = 0.5f - hs;
            d_out[B*T + b*T + r*RPC + w] = s_imp;
        }
    }
}

// =====================================================================
extern "C" void kernel_launch(void* const* d_in, const int* in_sizes, int n_in,
                              void* d_out, int out_size) {
    const float* inp      = (const float*)d_in[0];  // [B,T,F]
    const float* Wk       = (const float*)d_in[1];  // [F,U]
    const float* bk       = (const float*)d_in[2];  // [U]
    const float* Wv       = (const float*)d_in[3];  // [U,F]
    const float* bv       = (const float*)d_in[4];  // [F]
    const float* w_s      = (const float*)d_in[5];  // [S]
    const float* mem_keys = (const float*)d_in[6];  // [M, T*F]
    const float* mem_vals = (const float*)d_in[7];  // [M, F]

    fused_all<<<B*CPB, NTH>>>(inp, Wk, bk, Wv, bv, w_s, mem_keys, mem_vals,
                              (float*)d_out);
}